// round 1
// baseline (speedup 1.0000x reference)
#include <cuda_runtime.h>
#include <float.h>

// Problem constants (static per reference)
#define BATCH   8
#define SEQ     4096
#define NTOK    (BATCH*SEQ)     // 32768
#define DIM     1024
#define NEXP    64
#define NGRP    4
#define GRPSZ   16
#define KSEL    2

// Output layout (tuple-flatten, float32):
// idx [NTOK*2] | scores [NTOK*2] | probs_full [NTOK*64] | importance [64] | load [64]
#define OFF_IDX   0
#define OFF_SC    (NTOK*KSEL)                 // 65536
#define OFF_PROBS (2*NTOK*KSEL)               // 131072
#define OFF_IMP   (OFF_PROBS + NTOK*NEXP)     // 2228224
#define OFF_LOAD  (OFF_IMP + NEXP)            // 2228288

// Tiling
#define TILE_M  128
#define KT      32
#define NTHR    256
#define TM      8
#define TN      4
#define LGPITCH 72   // padded row for logits tile (>=68, %4==0, %32!=0)
#define XPITCH  33

__device__ int g_counts[NEXP];

__global__ void zero_kernel(float* out) {
    int t = threadIdx.x;
    if (t < NEXP) {
        out[OFF_IMP + t] = 0.0f;
        g_counts[t] = 0;
    }
}

__global__ void finalize_kernel(float* out) {
    int t = threadIdx.x;
    if (t < NEXP) {
        out[OFF_LOAD + t] = (float)g_counts[t] * (1.0f / (float)(NTOK * KSEL));
    }
}

__global__ __launch_bounds__(NTHR)
void router_kernel(const float* __restrict__ xg,
                   const float* __restrict__ Wg,
                   const float* __restrict__ We,
                   float* __restrict__ out) {
    // shared: union of {xs[128][33], ws[68][33]} and logits lg[128][72]
    __shared__ float smem[TILE_M * LGPITCH];     // 36864 B
    __shared__ int   cnt_s[NEXP];

    float* xs = smem;                    // [128][33] = 4224 floats
    float* ws = smem + TILE_M * XPITCH;  // [68][33]  = 2244 floats (fits: 4224+2244=6468 < 9216)
    float* lg = smem;                    // alias, used after K loop

    const int tid = threadIdx.x;
    const int tx  = tid & 15;
    const int ty  = tid >> 4;
    const int tok0 = blockIdx.x * TILE_M;

    if (tid < NEXP) cnt_s[tid] = 0;

    float acc[TM][TN];
#pragma unroll
    for (int m = 0; m < TM; ++m)
#pragma unroll
        for (int n = 0; n < TN; ++n) acc[m][n] = 0.0f;

    // group-logit accumulators: thread tid handles token tid/2, groups (tid&1)*2 + {0,1}
    const int gtok = tid >> 1;
    const int gbase2 = (tid & 1) * 2;
    float gacc0 = 0.0f, gacc1 = 0.0f;

    for (int k0 = 0; k0 < DIM; k0 += KT) {
        // load x tile [128][32] (float4, then scalar scatter into padded rows)
#pragma unroll
        for (int j = 0; j < 4; ++j) {
            int s = tid + j * NTHR;            // 0..1023 float4 slots
            int t = s >> 3, kv = s & 7;
            float4 v = *(const float4*)(xg + (size_t)(tok0 + t) * DIM + k0 + kv * 4);
            float* dst = &xs[t * XPITCH + kv * 4];
            dst[0] = v.x; dst[1] = v.y; dst[2] = v.z; dst[3] = v.w;
        }
        // load W tile [68][32]: rows 0..63 experts, 64..67 groups
        for (int s = tid; s < 68 * 8; s += NTHR) {
            int r = s >> 3, kv = s & 7;
            const float* src = (r < NEXP) ? (We + (size_t)r * DIM)
                                          : (Wg + (size_t)(r - NEXP) * DIM);
            float4 v = *(const float4*)(src + k0 + kv * 4);
            float* dst = &ws[r * XPITCH + kv * 4];
            dst[0] = v.x; dst[1] = v.y; dst[2] = v.z; dst[3] = v.w;
        }
        __syncthreads();

#pragma unroll 8
        for (int k = 0; k < KT; ++k) {
            float xr[TM], wr[TN];
#pragma unroll
            for (int m = 0; m < TM; ++m) xr[m] = xs[(ty * TM + m) * XPITCH + k];
#pragma unroll
            for (int n = 0; n < TN; ++n) wr[n] = ws[(tx * TN + n) * XPITCH + k];
#pragma unroll
            for (int m = 0; m < TM; ++m)
#pragma unroll
                for (int n = 0; n < TN; ++n) acc[m][n] = fmaf(xr[m], wr[n], acc[m][n]);
            // group logits
            float xv = xs[gtok * XPITCH + k];
            gacc0 = fmaf(xv, ws[(NEXP + gbase2 + 0) * XPITCH + k], gacc0);
            gacc1 = fmaf(xv, ws[(NEXP + gbase2 + 1) * XPITCH + k], gacc1);
        }
        __syncthreads();
    }

    // write logits into lg[128][72] (aliases xs/ws — safe after sync)
#pragma unroll
    for (int m = 0; m < TM; ++m)
#pragma unroll
        for (int n = 0; n < TN; ++n)
            lg[(ty * TM + m) * LGPITCH + tx * TN + n] = acc[m][n];
    lg[gtok * LGPITCH + NEXP + gbase2 + 0] = gacc0;
    lg[gtok * LGPITCH + NEXP + gbase2 + 1] = gacc1;
    __syncthreads();

    // epilogue: one thread per token (tid < 128)
    if (tid < TILE_M) {
        float* row = &lg[tid * LGPITCH];
        // argmax of group logits (first-max tie-break, matches jnp.argmax)
        int g = 0;
        float gbest = row[NEXP + 0];
#pragma unroll
        for (int j = 1; j < NGRP; ++j) {
            float v = row[NEXP + j];
            if (v > gbest) { gbest = v; g = j; }
        }
        const int ebase = g * GRPSZ;

        // in-group max and top-2 (jax top_k tie order: lower index first)
        float v1 = -FLT_MAX, v2 = -FLT_MAX;
        int i1 = 0, i2 = 0;
#pragma unroll
        for (int e = 0; e < GRPSZ; ++e) {
            float v = row[ebase + e];
            if (v > v1) { v2 = v1; i2 = i1; v1 = v; i1 = e; }
            else if (v > v2) { v2 = v; i2 = e; }
        }
        // masked softmax over 64 (out-of-group -> exactly 0)
        float denom = 0.0f;
        float ex[GRPSZ];
#pragma unroll
        for (int e = 0; e < GRPSZ; ++e) {
            ex[e] = __expf(row[ebase + e] - v1);
            denom += ex[e];
        }
        float inv = 1.0f / denom;
#pragma unroll
        for (int e = 0; e < NEXP; ++e) {
            float p = (e >= ebase && e < ebase + GRPSZ) ? ex[e - ebase] * inv : 0.0f;
            row[e] = p;
        }
        // top-2 scores softmax
        float e2 = __expf(v2 - v1);
        float s1 = 1.0f / (1.0f + e2);
        float s2 = e2 * s1;
        int tok = tok0 + tid;
        out[OFF_IDX + tok * 2 + 0] = (float)(ebase + i1);
        out[OFF_IDX + tok * 2 + 1] = (float)(ebase + i2);
        out[OFF_SC  + tok * 2 + 0] = s1;
        out[OFF_SC  + tok * 2 + 1] = s2;
        atomicAdd(&cnt_s[ebase + i1], 1);
        atomicAdd(&cnt_s[ebase + i2], 1);
    }
    __syncthreads();

    // store probs_full tile (coalesced float4)
    for (int i = tid; i < TILE_M * (NEXP / 4); i += NTHR) {
        int t = i >> 4, c = i & 15;
        float4 v = *(const float4*)&lg[t * LGPITCH + c * 4];
        *(float4*)(out + OFF_PROBS + (size_t)(tok0 + t) * NEXP + c * 4) = v;
    }
    // importance column sums + counts flush
    if (tid < NEXP) {
        float s = 0.0f;
        for (int t = 0; t < TILE_M; ++t) s += lg[t * LGPITCH + tid];
        atomicAdd(&out[OFF_IMP + tid], s * (1.0f / (float)NTOK));
        int c = cnt_s[tid];
        if (c) atomicAdd(&g_counts[tid], c);
    }
}

extern "C" void kernel_launch(void* const* d_in, const int* in_sizes, int n_in,
                              void* d_out, int out_size) {
    const float *x = nullptr, *Wg = nullptr, *We = nullptr;
    for (int i = 0; i < n_in; ++i) {
        if (in_sizes[i] == NTOK * DIM)      x  = (const float*)d_in[i];
        else if (in_sizes[i] == NGRP * DIM) Wg = (const float*)d_in[i];
        else if (in_sizes[i] == NEXP * DIM) We = (const float*)d_in[i];
    }
    float* out = (float*)d_out;
    zero_kernel<<<1, 64>>>(out);
    router_kernel<<<NTOK / TILE_M, NTHR>>>(x, Wg, We, out);
    finalize_kernel<<<1, 64>>>(out);
}

// round 2
// speedup vs baseline: 1.0015x; 1.0015x over previous
#include <cuda_runtime.h>
#include <float.h>

// Problem constants (static per reference)
#define BATCH   8
#define SEQ     4096
#define NTOK    (BATCH*SEQ)     // 32768
#define DIM     1024
#define NEXP    64
#define NGRP    4
#define GRPSZ   16
#define KSEL    2

// Output layout (tuple-flatten, float32):
// idx [NTOK*2] | scores [NTOK*2] | probs_full [NTOK*64] | importance [64] | load [64]
#define OFF_IDX   0
#define OFF_SC    (NTOK*KSEL)
#define OFF_PROBS (2*NTOK*KSEL)
#define OFF_IMP   (OFF_PROBS + NTOK*NEXP)
#define OFF_LOAD  (OFF_IMP + NEXP)

// Tiling
#define TILE_M  128
#define KT      32      // k per tile; 16 f32x2 pairs
#define NTHR    256
#define TM      8
#define TN      4
#define LGPITCH 72      // padded row for logits tile
#define XPITCH  34      // even -> 8B-aligned k-pairs
#define WPITCH  32      // exact; bank conflicts handled by XOR swizzle

typedef unsigned long long ull;

__device__ int g_counts[NEXP];

__device__ __forceinline__ void ffma2(ull& d, ull a, ull b) {
    asm("fma.rn.f32x2 %0, %1, %2, %0;" : "+l"(d) : "l"(a), "l"(b));
}
__device__ __forceinline__ float ull_hsum(ull v) {
    float lo, hi;
    asm("mov.b64 {%0,%1}, %2;" : "=f"(lo), "=f"(hi) : "l"(v));
    return lo + hi;
}

__global__ void zero_kernel(float* out) {
    int t = threadIdx.x;
    if (t < NEXP) {
        out[OFF_IMP + t] = 0.0f;
        g_counts[t] = 0;
    }
}

__global__ void finalize_kernel(float* out) {
    int t = threadIdx.x;
    if (t < NEXP) {
        out[OFF_LOAD + t] = (float)g_counts[t] * (1.0f / (float)(NTOK * KSEL));
    }
}

__global__ __launch_bounds__(NTHR, 2)
void router_kernel(const float* __restrict__ xg,
                   const float* __restrict__ Wg,
                   const float* __restrict__ We,
                   float* __restrict__ out) {
    // shared: union of {xs[128][34], ws[68][32]} and logits lg[128][72]
    __shared__ float smem[TILE_M * LGPITCH];     // 36864 B
    __shared__ int   cnt_s[NEXP];

    float* xs = smem;                      // 128*34 = 4352 floats
    float* ws = smem + TILE_M * XPITCH;    // 68*32  = 2176 floats (6528 < 9216)
    float* lg = smem;                      // alias after K loop

    const int tid = threadIdx.x;
    const int tx  = tid & 15;              // expert-dim thread coord (16)
    const int ty  = tid >> 4;              // token-dim thread coord (16)
    const int tok0 = blockIdx.x * TILE_M;

    if (tid < NEXP) cnt_s[tid] = 0;

    ull acc2[TM][TN];
#pragma unroll
    for (int m = 0; m < TM; ++m)
#pragma unroll
        for (int n = 0; n < TN; ++n) acc2[m][n] = 0ull;

    // group logits: this thread computes groups {gb, gb+1} for token row grow
    const int gb   = (tx & 1) * 2;
    const int grow = ty * TM + (tx >> 1);
    ull gacc2a = 0ull, gacc2b = 0ull;

    // ws swizzle: element (r,k) stored at r*32 + 2*( (k>>1) ^ ((r>>2)&15) ^ ((r&3)<<2) ) + (k&1)
    const int swz_base = tx;  // (r>>2) for r = tx*4+n

    for (int k0 = 0; k0 < DIM; k0 += KT) {
        // ---- load x tile [128][32] into xs (pitch 34), float2 pairs ----
#pragma unroll
        for (int j = 0; j < 4; ++j) {
            int s = tid + j * NTHR;        // 0..1023 float4 slots
            int t = s >> 3, kv = s & 7;
            float4 v = *(const float4*)(xg + (size_t)(tok0 + t) * DIM + k0 + kv * 4);
            float* dst = &xs[t * XPITCH + kv * 4];
            *(float2*)(dst + 0) = make_float2(v.x, v.y);
            *(float2*)(dst + 2) = make_float2(v.z, v.w);
        }
        // ---- load W tile [68][32] into ws with XOR swizzle ----
        for (int s = tid; s < 68 * 8; s += NTHR) {
            int r = s >> 3, kv = s & 7;
            const float* src = (r < NEXP) ? (We + (size_t)r * DIM)
                                          : (Wg + (size_t)(r - NEXP) * DIM);
            float4 v = *(const float4*)(src + k0 + kv * 4);
            int swz = ((r >> 2) & 15) ^ ((r & 3) << 2);
            int kp0 = kv * 2;
            float* base = &ws[r * WPITCH];
            *(float2*)(base + 2 * (kp0 ^ swz))       = make_float2(v.x, v.y);
            *(float2*)(base + 2 * ((kp0 + 1) ^ swz)) = make_float2(v.z, v.w);
        }
        __syncthreads();

        const float* xrow = &xs[ty * TM * XPITCH];
        const float* grow_p = &xs[grow * XPITCH];
#pragma unroll
        for (int kp = 0; kp < KT / 2; ++kp) {
            ull xr2[TM], wr2[TN];
#pragma unroll
            for (int m = 0; m < TM; ++m)
                xr2[m] = *(const ull*)(xrow + m * XPITCH + kp * 2);
#pragma unroll
            for (int n = 0; n < TN; ++n) {
                int slot = kp ^ swz_base ^ (n << 2);
                wr2[n] = *(const ull*)(&ws[(tx * TN + n) * WPITCH + 2 * slot]);
            }
#pragma unroll
            for (int m = 0; m < TM; ++m)
#pragma unroll
                for (int n = 0; n < TN; ++n)
                    ffma2(acc2[m][n], xr2[m], wr2[n]);

            // group logits (rows 64..67, swz = ((r&3)<<2) since (r>>2)&15 == 0)
            ull xg2 = *(const ull*)(grow_p + kp * 2);
            ull wg0 = *(const ull*)(&ws[(NEXP + gb) * WPITCH     + 2 * (kp ^ ((gb    ) << 2))]);
            ull wg1 = *(const ull*)(&ws[(NEXP + gb + 1) * WPITCH + 2 * (kp ^ ((gb + 1) << 2))]);
            ffma2(gacc2a, xg2, wg0);
            ffma2(gacc2b, xg2, wg1);
        }
        __syncthreads();
    }

    // write logits into lg[128][72] (aliases xs/ws — safe after sync)
#pragma unroll
    for (int m = 0; m < TM; ++m)
#pragma unroll
        for (int n = 0; n < TN; ++n)
            lg[(ty * TM + m) * LGPITCH + tx * TN + n] = ull_hsum(acc2[m][n]);
    lg[grow * LGPITCH + NEXP + gb + 0] = ull_hsum(gacc2a);
    lg[grow * LGPITCH + NEXP + gb + 1] = ull_hsum(gacc2b);
    __syncthreads();

    // epilogue: one thread per token (tid < 128)
    if (tid < TILE_M) {
        float* row = &lg[tid * LGPITCH];
        // argmax of group logits (first-max tie-break, matches jnp.argmax)
        int g = 0;
        float gbest = row[NEXP + 0];
#pragma unroll
        for (int j = 1; j < NGRP; ++j) {
            float v = row[NEXP + j];
            if (v > gbest) { gbest = v; g = j; }
        }
        const int ebase = g * GRPSZ;

        // in-group top-2 (lower index wins ties, matches jax top_k)
        float v1 = -FLT_MAX, v2 = -FLT_MAX;
        int i1 = 0, i2 = 0;
#pragma unroll
        for (int e = 0; e < GRPSZ; ++e) {
            float v = row[ebase + e];
            if (v > v1) { v2 = v1; i2 = i1; v1 = v; i1 = e; }
            else if (v > v2) { v2 = v; i2 = e; }
        }
        // masked softmax over 64 (out-of-group -> exactly 0)
        float denom = 0.0f;
        float ex[GRPSZ];
#pragma unroll
        for (int e = 0; e < GRPSZ; ++e) {
            ex[e] = __expf(row[ebase + e] - v1);
            denom += ex[e];
        }
        float inv = 1.0f / denom;
#pragma unroll
        for (int e = 0; e < NEXP; ++e) {
            float p = (e >= ebase && e < ebase + GRPSZ) ? ex[e - ebase] * inv : 0.0f;
            row[e] = p;
        }
        // top-2 scores softmax
        float e2 = __expf(v2 - v1);
        float s1 = 1.0f / (1.0f + e2);
        float s2 = e2 * s1;
        int tok = tok0 + tid;
        out[OFF_IDX + tok * 2 + 0] = (float)(ebase + i1);
        out[OFF_IDX + tok * 2 + 1] = (float)(ebase + i2);
        out[OFF_SC  + tok * 2 + 0] = s1;
        out[OFF_SC  + tok * 2 + 1] = s2;
        atomicAdd(&cnt_s[ebase + i1], 1);
        atomicAdd(&cnt_s[ebase + i2], 1);
    }
    __syncthreads();

    // store probs_full tile (coalesced float4)
    for (int i = tid; i < TILE_M * (NEXP / 4); i += NTHR) {
        int t = i >> 4, c = i & 15;
        float4 v = *(const float4*)&lg[t * LGPITCH + c * 4];
        *(float4*)(out + OFF_PROBS + (size_t)(tok0 + t) * NEXP + c * 4) = v;
    }
    // importance column sums + counts flush
    if (tid < NEXP) {
        float s = 0.0f;
        for (int t = 0; t < TILE_M; ++t) s += lg[t * LGPITCH + tid];
        atomicAdd(&out[OFF_IMP + tid], s * (1.0f / (float)NTOK));
        int c = cnt_s[tid];
        if (c) atomicAdd(&g_counts[tid], c);
    }
}

extern "C" void kernel_launch(void* const* d_in, const int* in_sizes, int n_in,
                              void* d_out, int out_size) {
    const float *x = nullptr, *Wg = nullptr, *We = nullptr;
    for (int i = 0; i < n_in; ++i) {
        if (in_sizes[i] == NTOK * DIM)      x  = (const float*)d_in[i];
        else if (in_sizes[i] == NGRP * DIM) Wg = (const float*)d_in[i];
        else if (in_sizes[i] == NEXP * DIM) We = (const float*)d_in[i];
    }
    float* out = (float*)d_out;
    zero_kernel<<<1, 64>>>(out);
    router_kernel<<<NTOK / TILE_M, NTHR>>>(x, Wg, We, out);
    finalize_kernel<<<1, 64>>>(out);
}

// round 8
// speedup vs baseline: 1.6363x; 1.6339x over previous
#include <cuda_runtime.h>
#include <cuda_bf16.h>
#include <float.h>
#include <stdint.h>

// ---------------- problem constants ----------------
#define NTOK   32768
#define DIM    1024
#define NEXP   64
#define NGRP   4
#define GRPSZ  16

// output layout (float32): idx | scores | probs_full | importance | load
#define OFF_IDX   0
#define OFF_SC    (NTOK*2)
#define OFF_PROBS (NTOK*4)
#define OFF_IMP   (OFF_PROBS + NTOK*NEXP)
#define OFF_LOAD  (OFF_IMP + NEXP)

// ---------------- tiling ----------------
#define TILE_M 128
#define NPAD   72            // 64 experts + 4 groups + 4 zero rows
#define KC     64            // K elements per chunk
#define NCHUNK (DIM/KC)      // 16
#define NTHR   256
#define NWARP  8

// smem (dynamic, bytes): 3 bf16 planes for A and B, 128B rows, swizzled
#define A_PL   (TILE_M*128)          // 16384 per plane
#define SM_A   0
#define B_PL   (NPAD*128)            // 9216 per plane
#define SM_B   (3*A_PL)              // 49152
#define SM_TOTAL (SM_B + 3*B_PL)     // 76800

#define LGP 76   // logits/probs staging pitch (floats)

__device__ int g_counts[NEXP];

// ---------------- helpers ----------------
__device__ __forceinline__ uint32_t smem_u32(const void* p) {
    return (uint32_t)__cvta_generic_to_shared(p);
}

__device__ __forceinline__ void ldmx4(uint32_t addr, uint32_t* r) {
    asm volatile("ldmatrix.sync.aligned.m8n8.x4.shared.b16 {%0,%1,%2,%3}, [%4];"
                 : "=r"(r[0]), "=r"(r[1]), "=r"(r[2]), "=r"(r[3]) : "r"(addr));
}
__device__ __forceinline__ void ldmx2(uint32_t addr, uint32_t* r) {
    asm volatile("ldmatrix.sync.aligned.m8n8.x2.shared.b16 {%0,%1}, [%2];"
                 : "=r"(r[0]), "=r"(r[1]) : "r"(addr));
}
__device__ __forceinline__ void mma16816(float* d, const uint32_t* a,
                                         uint32_t b0, uint32_t b1) {
    asm volatile("mma.sync.aligned.m16n8k16.row.col.f32.bf16.bf16.f32 "
                 "{%0,%1,%2,%3}, {%4,%5,%6,%7}, {%8,%9}, {%0,%1,%2,%3};"
                 : "+f"(d[0]), "+f"(d[1]), "+f"(d[2]), "+f"(d[3])
                 : "r"(a[0]), "r"(a[1]), "r"(a[2]), "r"(a[3]), "r"(b0), "r"(b1));
}

__device__ __forceinline__ uint32_t pack2(float a, float b) {
    __nv_bfloat162 t = __floats2bfloat162_rn(a, b);
    return *reinterpret_cast<uint32_t*>(&t);
}
// fp32x4 -> 3 bf16 planes (hi/mid/lo), each as 2x uint32 (4 bf16)
__device__ __forceinline__ void cvt3x4(float4 v, uint2& h, uint2& m, uint2& l) {
    float f[4] = {v.x, v.y, v.z, v.w};
    float fm[4], fl[4];
#pragma unroll
    for (int i = 0; i < 4; ++i) {
        __nv_bfloat16 bh = __float2bfloat16_rn(f[i]);
        float r1 = f[i] - __bfloat162float(bh);
        __nv_bfloat16 bm = __float2bfloat16_rn(r1);
        fl[i] = r1 - __bfloat162float(bm);
        fm[i] = r1;      // re-rounded by pack2
        f[i]  = __bfloat162float(bh); // re-rounded exact
    }
    h = make_uint2(pack2(f[0], f[1]), pack2(f[2], f[3]));
    m = make_uint2(pack2(fm[0], fm[1]), pack2(fm[2], fm[3]));
    l = make_uint2(pack2(fl[0], fl[1]), pack2(fl[2], fl[3]));
}

// ---------------- small kernels ----------------
__global__ void zero_kernel(float* out) {
    int t = threadIdx.x;
    if (t < NEXP) { out[OFF_IMP + t] = 0.0f; g_counts[t] = 0; }
}
__global__ void finalize_kernel(float* out) {
    int t = threadIdx.x;
    if (t < NEXP) out[OFF_LOAD + t] = (float)g_counts[t] * (1.0f / (float)(NTOK * 2));
}

// ---------------- main kernel ----------------
__global__ __launch_bounds__(NTHR, 2)
void router_mma(const float* __restrict__ xg,
                const float* __restrict__ Wg,
                const float* __restrict__ We,
                float* __restrict__ out) {
    extern __shared__ char smem[];
    __shared__ int cnt_s[NEXP];
    const uint32_t sb = smem_u32(smem);
    const int tid = threadIdx.x;
    const int w   = tid >> 5;
    const int L   = tid & 31;
    const int tok0 = blockIdx.x * TILE_M;

    if (tid < NEXP) cnt_s[tid] = 0;

    float acc[9][4];
#pragma unroll
    for (int t = 0; t < 9; ++t)
#pragma unroll
        for (int i = 0; i < 4; ++i) acc[t][i] = 0.0f;

    // ldmatrix A lane addressing: row = 16w + (L&15), chunk = ks*2 + (L>>4)
    const int rowA  = 16 * w + (L & 15);
    const uint32_t aRowOff = rowA * 128;
    const int sA    = rowA & 7;
    const int aHi   = L >> 4;
    // ldmatrix B pair addressing
    const int bSel  = (L >> 4) & 1;       // tile_a vs tile_b
    const int bKbit = (L >> 3) & 1;       // k-chunk within slab
    const int bR7   = L & 7;

    for (int c = 0; c < NCHUNK; ++c) {
        const int k0 = c * KC;
        // prefetch x tile [128 x 64] fp32 (coalesced float4)
        float4 xv[8];
#pragma unroll
        for (int j = 0; j < 8; ++j) {
            int idx = tid + j * NTHR;             // 2048 float4 slots
            int row = idx >> 4, c4 = idx & 15;
            xv[j] = *(const float4*)(xg + (size_t)(tok0 + row) * DIM + k0 + c4 * 4);
        }
        __syncthreads();   // previous chunk's mma reads complete

        // A planes: convert + swizzled store (16B-chunk XOR by row&7)
#pragma unroll
        for (int j = 0; j < 8; ++j) {
            int idx = tid + j * NTHR;
            int row = idx >> 4, c4 = idx & 15;
            uint2 h, m, l;
            cvt3x4(xv[j], h, m, l);
            uint32_t off = row * 128 + (((c4 >> 1) ^ (row & 7)) << 4) + ((c4 & 1) << 3);
            *(uint2*)(smem + SM_A + 0 * A_PL + off) = h;
            *(uint2*)(smem + SM_A + 1 * A_PL + off) = m;
            *(uint2*)(smem + SM_A + 2 * A_PL + off) = l;
        }
        // B planes [72 x 64]: rows 0..63 experts, 64..67 groups, 68..71 zero
        for (int i = tid; i < NPAD * 16; i += NTHR) {
            int r = i >> 4, c4 = i & 15;
            float4 v = make_float4(0.f, 0.f, 0.f, 0.f);
            if (r < NEXP)          v = *(const float4*)(We + (size_t)r * DIM + k0 + c4 * 4);
            else if (r < NEXP + 4) v = *(const float4*)(Wg + (size_t)(r - NEXP) * DIM + k0 + c4 * 4);
            uint2 h, m, l;
            cvt3x4(v, h, m, l);
            uint32_t off = r * 128 + (((c4 >> 1) ^ (r & 7)) << 4) + ((c4 & 1) << 3);
            *(uint2*)(smem + SM_B + 0 * B_PL + off) = h;
            *(uint2*)(smem + SM_B + 1 * B_PL + off) = m;
            *(uint2*)(smem + SM_B + 2 * B_PL + off) = l;
        }
        __syncthreads();

        // mma over 4 k-slabs of 16
#pragma unroll
        for (int ks = 0; ks < 4; ++ks) {
            uint32_t Ah[4], Am[4], Al[4];
            {
                uint32_t aoff = aRowOff + ((((ks * 2) + aHi) ^ sA) << 4);
                ldmx4(sb + SM_A + 0 * A_PL + aoff, Ah);
                ldmx4(sb + SM_A + 1 * A_PL + aoff, Am);
                ldmx4(sb + SM_A + 2 * A_PL + aoff, Al);
            }
#pragma unroll
            for (int j = 0; j < 4; ++j) {
                uint32_t Bh[4], Bm[4], Bl[4];
                int brow = (2 * j + bSel) * 8 + bR7;
                uint32_t boff = brow * 128 + ((((ks * 2) + bKbit) ^ (brow & 7)) << 4);
                ldmx4(sb + SM_B + 0 * B_PL + boff, Bh);
                ldmx4(sb + SM_B + 1 * B_PL + boff, Bm);
                ldmx4(sb + SM_B + 2 * B_PL + boff, Bl);
                // tile 2j
                mma16816(acc[2*j],   Ah, Bh[0], Bh[1]);
                mma16816(acc[2*j],   Ah, Bm[0], Bm[1]);
                mma16816(acc[2*j],   Am, Bh[0], Bh[1]);
                mma16816(acc[2*j],   Am, Bm[0], Bm[1]);
                mma16816(acc[2*j],   Ah, Bl[0], Bl[1]);
                mma16816(acc[2*j],   Al, Bh[0], Bh[1]);
                // tile 2j+1
                mma16816(acc[2*j+1], Ah, Bh[2], Bh[3]);
                mma16816(acc[2*j+1], Ah, Bm[2], Bm[3]);
                mma16816(acc[2*j+1], Am, Bh[2], Bh[3]);
                mma16816(acc[2*j+1], Am, Bm[2], Bm[3]);
                mma16816(acc[2*j+1], Ah, Bl[2], Bl[3]);
                mma16816(acc[2*j+1], Al, Bh[2], Bh[3]);
            }
            {   // last n-tile (cols 64..71)
                uint32_t Bh[2], Bm[2], Bl[2];
                int brow = 64 + bR7;
                uint32_t boff = brow * 128 + ((((ks * 2) + bKbit) ^ (brow & 7)) << 4);
                ldmx2(sb + SM_B + 0 * B_PL + boff, Bh);
                ldmx2(sb + SM_B + 1 * B_PL + boff, Bm);
                ldmx2(sb + SM_B + 2 * B_PL + boff, Bl);
                mma16816(acc[8], Ah, Bh[0], Bh[1]);
                mma16816(acc[8], Ah, Bm[0], Bm[1]);
                mma16816(acc[8], Am, Bh[0], Bh[1]);
                mma16816(acc[8], Am, Bm[0], Bm[1]);
                mma16816(acc[8], Ah, Bl[0], Bl[1]);
                mma16816(acc[8], Al, Bh[0], Bh[1]);
            }
        }
    }
    __syncthreads();   // all mma done; smem free for logits staging

    float* lg = (float*)smem;   // [128][LGP]
    {
        int r0 = 16 * w + (L >> 2);
        int r1 = r0 + 8;
        int cb = 2 * (L & 3);
#pragma unroll
        for (int t = 0; t < 9; ++t) {
            *(float2*)&lg[r0 * LGP + t * 8 + cb] = make_float2(acc[t][0], acc[t][1]);
            *(float2*)&lg[r1 * LGP + t * 8 + cb] = make_float2(acc[t][2], acc[t][3]);
        }
    }
    __syncthreads();

    if (tid < TILE_M) {   // one thread per token
        float d[68];
#pragma unroll
        for (int e = 0; e < 68; ++e) d[e] = lg[tid * LGP + e];

        // group argmax (first-max tie-break == jnp.argmax)
        int g = 0; float gbest = d[NEXP + 0];
#pragma unroll
        for (int j = 1; j < NGRP; ++j)
            if (d[NEXP + j] > gbest) { gbest = d[NEXP + j]; g = j; }
        const int ebase = g * GRPSZ;

        // in-group top-2 (lower index wins ties, matches jax top_k)
        float v1 = -FLT_MAX, v2 = -FLT_MAX; int i1 = 0, i2 = 0;
#pragma unroll
        for (int e = 0; e < GRPSZ; ++e) {
            float v = d[ebase + e];
            if (v > v1) { v2 = v1; i2 = i1; v1 = v; i1 = e; }
            else if (v > v2) { v2 = v; i2 = e; }
        }
        // masked softmax: out-of-group exactly 0
        float ex[GRPSZ], denom = 0.f;
#pragma unroll
        for (int e = 0; e < GRPSZ; ++e) { ex[e] = __expf(d[ebase + e] - v1); denom += ex[e]; }
        float inv = 1.f / denom;

        float e2v = __expf(v2 - v1);
        float s1 = 1.f / (1.f + e2v);
        float s2 = e2v * s1;
        int tok = tok0 + tid;
        out[OFF_IDX + tok * 2 + 0] = (float)(ebase + i1);
        out[OFF_IDX + tok * 2 + 1] = (float)(ebase + i2);
        out[OFF_SC  + tok * 2 + 0] = s1;
        out[OFF_SC  + tok * 2 + 1] = s2;
        atomicAdd(&cnt_s[ebase + i1], 1);
        atomicAdd(&cnt_s[ebase + i2], 1);

        // overwrite row with probs
#pragma unroll
        for (int q = 0; q < 16; ++q) {
            float4 pv;
            float* pf = (float*)&pv;
#pragma unroll
            for (int u = 0; u < 4; ++u) {
                int e = q * 4 + u;
                pf[u] = (e >= ebase && e < ebase + GRPSZ) ? ex[e - ebase] * inv : 0.0f;
            }
            *(float4*)&lg[tid * LGP + q * 4] = pv;
        }
    }
    __syncthreads();

    // coalesced probs store
    for (int i = tid; i < TILE_M * 16; i += NTHR) {
        int t = i >> 4, q = i & 15;
        float4 v = *(const float4*)&lg[t * LGP + q * 4];
        *(float4*)(out + OFF_PROBS + (size_t)(tok0 + t) * NEXP + q * 4) = v;
    }
    // importance + counts
    if (tid < NEXP) {
        float s = 0.f;
        for (int t = 0; t < TILE_M; ++t) s += lg[t * LGP + tid];
        atomicAdd(&out[OFF_IMP + tid], s * (1.0f / (float)NTOK));
        int cc = cnt_s[tid];
        if (cc) atomicAdd(&g_counts[tid], cc);
    }
}

// ---------------- launch ----------------
extern "C" void kernel_launch(void* const* d_in, const int* in_sizes, int n_in,
                              void* d_out, int out_size) {
    const float *x = nullptr, *Wg = nullptr, *We = nullptr;
    for (int i = 0; i < n_in; ++i) {
        if (in_sizes[i] == NTOK * DIM)      x  = (const float*)d_in[i];
        else if (in_sizes[i] == NGRP * DIM) Wg = (const float*)d_in[i];
        else if (in_sizes[i] == NEXP * DIM) We = (const float*)d_in[i];
    }
    float* out = (float*)d_out;
    cudaFuncSetAttribute(router_mma, cudaFuncAttributeMaxDynamicSharedMemorySize, SM_TOTAL);
    zero_kernel<<<1, 64>>>(out);
    router_mma<<<NTOK / TILE_M, NTHR, SM_TOTAL>>>(x, Wg, We, out);
    finalize_kernel<<<1, 64>>>(out);
}

// round 12
// speedup vs baseline: 2.6502x; 1.6197x over previous
#include <cuda_runtime.h>
#include <cuda_fp16.h>
#include <float.h>
#include <stdint.h>

// ---------------- problem constants ----------------
#define NTOK   32768
#define DIM    1024
#define NEXP   64
#define NGRP   4
#define GRPSZ  16

// output layout (float32): idx | scores | probs_full | importance | load
#define OFF_IDX   0
#define OFF_SC    (NTOK*2)
#define OFF_PROBS (NTOK*4)
#define OFF_IMP   (OFF_PROBS + NTOK*NEXP)
#define OFF_LOAD  (OFF_IMP + NEXP)

// ---------------- tiling ----------------
#define TILE_M 128
#define NPAD   72            // 64 experts + 4 groups + 4 zero rows
#define KC     64            // K elements per chunk (64 fp16 = 128B row)
#define NCHUNK (DIM/KC)      // 16
#define NTHR   256

#define WSCALE    64.0f
#define INV_WSCALE 0.015625f

// smem (dynamic, bytes): 2 fp16 planes for A and B, 128B rows, swizzled
#define A_PL   (TILE_M*128)          // 16384 per plane
#define SM_A   0
#define B_PL   (NPAD*128)            // 9216 per plane
#define SM_B   (2*A_PL)              // 32768
#define SM_TOTAL (SM_B + 2*B_PL)     // 51200

#define LGP 76   // logits/probs staging pitch (floats)

__device__ int g_counts[NEXP];
__device__ __align__(16) __half W_pre[2][NPAD*DIM];   // pre-split scaled W planes

// ---------------- helpers ----------------
__device__ __forceinline__ uint32_t smem_u32(const void* p) {
    return (uint32_t)__cvta_generic_to_shared(p);
}
__device__ __forceinline__ void ldmx4(uint32_t addr, uint32_t* r) {
    asm volatile("ldmatrix.sync.aligned.m8n8.x4.shared.b16 {%0,%1,%2,%3}, [%4];"
                 : "=r"(r[0]), "=r"(r[1]), "=r"(r[2]), "=r"(r[3]) : "r"(addr));
}
__device__ __forceinline__ void ldmx2(uint32_t addr, uint32_t* r) {
    asm volatile("ldmatrix.sync.aligned.m8n8.x2.shared.b16 {%0,%1}, [%2];"
                 : "=r"(r[0]), "=r"(r[1]) : "r"(addr));
}
__device__ __forceinline__ void mma16816(float* d, const uint32_t* a,
                                         uint32_t b0, uint32_t b1) {
    asm volatile("mma.sync.aligned.m16n8k16.row.col.f32.f16.f16.f32 "
                 "{%0,%1,%2,%3}, {%4,%5,%6,%7}, {%8,%9}, {%0,%1,%2,%3};"
                 : "+f"(d[0]), "+f"(d[1]), "+f"(d[2]), "+f"(d[3])
                 : "r"(a[0]), "r"(a[1]), "r"(a[2]), "r"(a[3]), "r"(b0), "r"(b1));
}
__device__ __forceinline__ uint32_t pack2h(float a, float b) {
    __half2 t = __floats2half2_rn(a, b);
    return *reinterpret_cast<uint32_t*>(&t);
}
// fp32x4 -> 2 fp16 planes (hi/mid), each as 2x uint32 (4 halves)
__device__ __forceinline__ void cvt2x4(float4 v, uint2& h, uint2& m) {
    float f[4] = {v.x, v.y, v.z, v.w};
    float fm[4];
#pragma unroll
    for (int i = 0; i < 4; ++i) {
        __half hh = __float2half_rn(f[i]);
        fm[i] = f[i] - __half2float(hh);     // exact in fp32
        f[i]  = __half2float(hh);            // exact
    }
    h = make_uint2(pack2h(f[0], f[1]), pack2h(f[2], f[3]));
    m = make_uint2(pack2h(fm[0], fm[1]), pack2h(fm[2], fm[3]));
}

// ---------------- small kernels ----------------
__global__ void zero_kernel(float* out) {
    int t = threadIdx.x;
    if (t < NEXP) { out[OFF_IMP + t] = 0.0f; g_counts[t] = 0; }
}
__global__ void finalize_kernel(float* out) {
    int t = threadIdx.x;
    if (t < NEXP) out[OFF_LOAD + t] = (float)g_counts[t] * (1.0f / (float)(NTOK * 2));
}
// pre-split W (scaled by 64) into fp16 hi/mid planes
__global__ void prep_kernel(const float* __restrict__ Wg, const float* __restrict__ We) {
    int r = blockIdx.x;
    int t = threadIdx.x;
#pragma unroll
    for (int j = 0; j < 4; ++j) {
        int k = t + j * 256;
        float v = 0.0f;
        if (r < NEXP)          v = We[r * DIM + k];
        else if (r < NEXP + 4) v = Wg[(r - NEXP) * DIM + k];
        v *= WSCALE;
        __half h = __float2half_rn(v);
        float rm = v - __half2float(h);
        W_pre[0][r * DIM + k] = h;
        W_pre[1][r * DIM + k] = __float2half_rn(rm);
    }
}

// ---------------- main kernel ----------------
__global__ __launch_bounds__(NTHR, 2)
void router_mma(const float* __restrict__ xg,
                float* __restrict__ out) {
    extern __shared__ char smem[];
    __shared__ int cnt_s[NEXP];
    const uint32_t sb = smem_u32(smem);
    const int tid = threadIdx.x;
    const int w   = tid >> 5;
    const int L   = tid & 31;
    const int tok0 = blockIdx.x * TILE_M;

    if (tid < NEXP) cnt_s[tid] = 0;

    float acc[9][4];
#pragma unroll
    for (int t = 0; t < 9; ++t)
#pragma unroll
        for (int i = 0; i < 4; ++i) acc[t][i] = 0.0f;

    // ldmatrix A lane addressing: row = 16w + (L&15), chunk = ks*2 + (L>>4)
    const int rowA  = 16 * w + (L & 15);
    const uint32_t aRowOff = rowA * 128;
    const int sA    = rowA & 7;
    const int aHi   = L >> 4;
    // ldmatrix B pair addressing
    const int bSel  = (L >> 4) & 1;
    const int bKbit = (L >> 3) & 1;
    const int bR7   = L & 7;

    for (int c = 0; c < NCHUNK; ++c) {
        const int k0 = c * KC;
        // prefetch x tile [128 x 64] fp32 (coalesced float4)
        float4 xv[8];
#pragma unroll
        for (int j = 0; j < 8; ++j) {
            int idx = tid + j * NTHR;
            int row = idx >> 4, c4 = idx & 15;
            xv[j] = *(const float4*)(xg + (size_t)(tok0 + row) * DIM + k0 + c4 * 4);
        }
        __syncthreads();   // previous chunk's mma reads complete

        // A planes: convert + swizzled store (16B-chunk XOR by row&7)
#pragma unroll
        for (int j = 0; j < 8; ++j) {
            int idx = tid + j * NTHR;
            int row = idx >> 4, c4 = idx & 15;
            uint2 h, m;
            cvt2x4(xv[j], h, m);
            uint32_t off = row * 128 + (((c4 >> 1) ^ (row & 7)) << 4) + ((c4 & 1) << 3);
            *(uint2*)(smem + SM_A + 0 * A_PL + off) = h;
            *(uint2*)(smem + SM_A + 1 * A_PL + off) = m;
        }
        // B planes [72 x 64]: copy pre-split fp16 planes (16B per row-chunk)
        for (int i = tid; i < NPAD * 8; i += NTHR) {
            int r = i >> 3, c8 = i & 7;
            uint32_t off = r * 128 + ((c8 ^ (r & 7)) << 4);
            *(uint4*)(smem + SM_B + 0 * B_PL + off) =
                *(const uint4*)&W_pre[0][r * DIM + k0 + c8 * 8];
            *(uint4*)(smem + SM_B + 1 * B_PL + off) =
                *(const uint4*)&W_pre[1][r * DIM + k0 + c8 * 8];
        }
        __syncthreads();

        // mma over 4 k-slabs of 16
#pragma unroll
        for (int ks = 0; ks < 4; ++ks) {
            uint32_t Ah[4], Am[4];
            {
                uint32_t aoff = aRowOff + ((((ks * 2) + aHi) ^ sA) << 4);
                ldmx4(sb + SM_A + 0 * A_PL + aoff, Ah);
                ldmx4(sb + SM_A + 1 * A_PL + aoff, Am);
            }
#pragma unroll
            for (int j = 0; j < 4; ++j) {
                uint32_t Bh[4], Bm[4];
                int brow = (2 * j + bSel) * 8 + bR7;
                uint32_t boff = brow * 128 + ((((ks * 2) + bKbit) ^ (brow & 7)) << 4);
                ldmx4(sb + SM_B + 0 * B_PL + boff, Bh);
                ldmx4(sb + SM_B + 1 * B_PL + boff, Bm);
                // tile 2j:   hh + hm + mh
                mma16816(acc[2*j],   Ah, Bh[0], Bh[1]);
                mma16816(acc[2*j],   Ah, Bm[0], Bm[1]);
                mma16816(acc[2*j],   Am, Bh[0], Bh[1]);
                // tile 2j+1
                mma16816(acc[2*j+1], Ah, Bh[2], Bh[3]);
                mma16816(acc[2*j+1], Ah, Bm[2], Bm[3]);
                mma16816(acc[2*j+1], Am, Bh[2], Bh[3]);
            }
            {   // last n-tile (cols 64..71)
                uint32_t Bh[2], Bm[2];
                int brow = 64 + bR7;
                uint32_t boff = brow * 128 + ((((ks * 2) + bKbit) ^ (brow & 7)) << 4);
                ldmx2(sb + SM_B + 0 * B_PL + boff, Bh);
                ldmx2(sb + SM_B + 1 * B_PL + boff, Bm);
                mma16816(acc[8], Ah, Bh[0], Bh[1]);
                mma16816(acc[8], Ah, Bm[0], Bm[1]);
                mma16816(acc[8], Am, Bh[0], Bh[1]);
            }
        }
    }
    __syncthreads();   // all mma done; smem free for logits staging

    float* lg = (float*)smem;   // [128][LGP]
    {
        int r0 = 16 * w + (L >> 2);
        int r1 = r0 + 8;
        int cb = 2 * (L & 3);
#pragma unroll
        for (int t = 0; t < 9; ++t) {
            *(float2*)&lg[r0 * LGP + t * 8 + cb] = make_float2(acc[t][0], acc[t][1]);
            *(float2*)&lg[r1 * LGP + t * 8 + cb] = make_float2(acc[t][2], acc[t][3]);
        }
    }
    __syncthreads();

    if (tid < TILE_M) {   // one thread per token
        float d[68];
#pragma unroll
        for (int e = 0; e < 68; ++e) d[e] = lg[tid * LGP + e] * INV_WSCALE;

        // group argmax (first-max tie-break == jnp.argmax)
        int g = 0; float gbest = d[NEXP + 0];
#pragma unroll
        for (int j = 1; j < NGRP; ++j)
            if (d[NEXP + j] > gbest) { gbest = d[NEXP + j]; g = j; }
        const int ebase = g * GRPSZ;

        // in-group top-2 (lower index wins ties, matches jax top_k)
        float v1 = -FLT_MAX, v2 = -FLT_MAX; int i1 = 0, i2 = 0;
#pragma unroll
        for (int e = 0; e < GRPSZ; ++e) {
            float v = d[ebase + e];
            if (v > v1) { v2 = v1; i2 = i1; v1 = v; i1 = e; }
            else if (v > v2) { v2 = v; i2 = e; }
        }
        // masked softmax: out-of-group exactly 0
        float ex[GRPSZ], denom = 0.f;
#pragma unroll
        for (int e = 0; e < GRPSZ; ++e) { ex[e] = __expf(d[ebase + e] - v1); denom += ex[e]; }
        float inv = 1.f / denom;

        float e2v = __expf(v2 - v1);
        float s1 = 1.f / (1.f + e2v);
        float s2 = e2v * s1;
        int tok = tok0 + tid;
        out[OFF_IDX + tok * 2 + 0] = (float)(ebase + i1);
        out[OFF_IDX + tok * 2 + 1] = (float)(ebase + i2);
        out[OFF_SC  + tok * 2 + 0] = s1;
        out[OFF_SC  + tok * 2 + 1] = s2;
        atomicAdd(&cnt_s[ebase + i1], 1);
        atomicAdd(&cnt_s[ebase + i2], 1);

        // overwrite row with probs
#pragma unroll
        for (int q = 0; q < 16; ++q) {
            float4 pv;
            float* pf = (float*)&pv;
#pragma unroll
            for (int u = 0; u < 4; ++u) {
                int e = q * 4 + u;
                pf[u] = (e >= ebase && e < ebase + GRPSZ) ? ex[e - ebase] * inv : 0.0f;
            }
            *(float4*)&lg[tid * LGP + q * 4] = pv;
        }
    }
    __syncthreads();

    // coalesced probs store
    for (int i = tid; i < TILE_M * 16; i += NTHR) {
        int t = i >> 4, q = i & 15;
        float4 v = *(const float4*)&lg[t * LGP + q * 4];
        *(float4*)(out + OFF_PROBS + (size_t)(tok0 + t) * NEXP + q * 4) = v;
    }
    // importance + counts
    if (tid < NEXP) {
        float s = 0.f;
        for (int t = 0; t < TILE_M; ++t) s += lg[t * LGP + tid];
        atomicAdd(&out[OFF_IMP + tid], s * (1.0f / (float)NTOK));
        int cc = cnt_s[tid];
        if (cc) atomicAdd(&g_counts[tid], cc);
    }
}

// ---------------- launch ----------------
extern "C" void kernel_launch(void* const* d_in, const int* in_sizes, int n_in,
                              void* d_out, int out_size) {
    const float *x = nullptr, *Wg = nullptr, *We = nullptr;
    for (int i = 0; i < n_in; ++i) {
        if (in_sizes[i] == NTOK * DIM)      x  = (const float*)d_in[i];
        else if (in_sizes[i] == NGRP * DIM) Wg = (const float*)d_in[i];
        else if (in_sizes[i] == NEXP * DIM) We = (const float*)d_in[i];
    }
    float* out = (float*)d_out;
    cudaFuncSetAttribute(router_mma, cudaFuncAttributeMaxDynamicSharedMemorySize, SM_TOTAL);
    zero_kernel<<<1, 64>>>(out);
    prep_kernel<<<NPAD, 256>>>(Wg, We);
    router_mma<<<NTOK / TILE_M, NTHR, SM_TOTAL>>>(x, out);
    finalize_kernel<<<1, 64>>>(out);
}